// round 9
// baseline (speedup 1.0000x reference)
#include <cuda_runtime.h>
#include <cuda_bf16.h>
#include <cstdint>

#define T_STEPS 4096
#define ISZ 1024
#define HSZ 2048
#define OSZ 64
#define NBLK 148
#define RT 256

// ---------------- device scratch (no allocations allowed) -------------------
__device__ float g_xproj[(size_t)T_STEPS * 4 * HSZ];  // [t][gate*H + j]
__device__ unsigned short g_hb[2 * HSZ];              // double-buffered h (bf16)
__device__ __align__(128) unsigned g_flags[160];      // arrival flags, packed;
                                                      // [NBLK..159] = UINT_MAX pad

// ---------------- init: zero h buffers + barrier flags ----------------------
__global__ void init_kernel() {
    int i = blockIdx.x * blockDim.x + threadIdx.x;
    int n = blockDim.x * gridDim.x;
    for (int k = i; k < 2 * HSZ; k += n) g_hb[k] = 0;
    for (int k = i; k < 160; k += n) g_flags[k] = (k < NBLK) ? 0u : 0xFFFFFFFFu;
}

// ---------------- x-projection GEMM ------------------------------------------
#define BM 128
#define BN 64
#define BK 16

__global__ __launch_bounds__(256) void xproj_kernel(
    const float* __restrict__ A,
    const float* __restrict__ W0, const float* __restrict__ W1,
    const float* __restrict__ W2, const float* __restrict__ W3,
    const float* __restrict__ Wb0, const float* __restrict__ Wb1,
    const float* __restrict__ Wb2, const float* __restrict__ Wb3,
    const float* __restrict__ Ub0, const float* __restrict__ Ub1,
    const float* __restrict__ Ub2, const float* __restrict__ Ub3)
{
    __shared__ float As[BK][BM + 4];
    __shared__ float Bs[BK][BN + 4];
    const int bn = blockIdx.x;
    const int bm = blockIdx.y;
    const int gate = bn >> 5;
    const int j0 = (bn & 31) * BN;
    const float* W  = (gate == 0) ? W0  : (gate == 1) ? W1  : (gate == 2) ? W2  : W3;
    const float* Wb = (gate == 0) ? Wb0 : (gate == 1) ? Wb1 : (gate == 2) ? Wb2 : Wb3;
    const float* Ub = (gate == 0) ? Ub0 : (gate == 1) ? Ub1 : (gate == 2) ? Ub2 : Ub3;
    const int m0 = bm * BM;
    const int tid = threadIdx.x;
    const int tm = tid >> 4, tn = tid & 15;

    float acc[8][4];
#pragma unroll
    for (int i = 0; i < 8; i++)
#pragma unroll
        for (int j = 0; j < 4; j++) acc[i][j] = 0.f;

    for (int k0 = 0; k0 < ISZ; k0 += BK) {
#pragma unroll
        for (int it = 0; it < 2; it++) {
            int e = tid + it * 256;
            int row = e >> 2, kq = e & 3;
            float4 v = *(const float4*)(A + (size_t)(m0 + row) * ISZ + k0 + kq * 4);
            As[kq * 4 + 0][row] = v.x; As[kq * 4 + 1][row] = v.y;
            As[kq * 4 + 2][row] = v.z; As[kq * 4 + 3][row] = v.w;
        }
        {
            int row = tid >> 2, kq = tid & 3;
            float4 v = *(const float4*)(W + (size_t)(j0 + row) * ISZ + k0 + kq * 4);
            Bs[kq * 4 + 0][row] = v.x; Bs[kq * 4 + 1][row] = v.y;
            Bs[kq * 4 + 2][row] = v.z; Bs[kq * 4 + 3][row] = v.w;
        }
        __syncthreads();
#pragma unroll
        for (int k = 0; k < BK; k++) {
            float a[8], bb[4];
#pragma unroll
            for (int i = 0; i < 8; i++) a[i] = As[k][tm * 8 + i];
#pragma unroll
            for (int j = 0; j < 4; j++) bb[j] = Bs[k][tn * 4 + j];
#pragma unroll
            for (int i = 0; i < 8; i++)
#pragma unroll
                for (int j = 0; j < 4; j++)
                    acc[i][j] = fmaf(a[i], bb[j], acc[i][j]);
        }
        __syncthreads();
    }

    float bias[4];
#pragma unroll
    for (int j = 0; j < 4; j++) {
        int col = j0 + tn * 4 + j;
        bias[j] = Wb[col] + Ub[col];
    }
#pragma unroll
    for (int i = 0; i < 8; i++) {
        int row = m0 + tm * 8 + i;
        float4 v = make_float4(acc[i][0] + bias[0], acc[i][1] + bias[1],
                               acc[i][2] + bias[2], acc[i][3] + bias[3]);
        *(float4*)(g_xproj + (size_t)row * (4 * HSZ) + gate * HSZ + j0 + tn * 4) = v;
    }
}

// ---------------- persistent recurrence kernel ------------------------------
#define WS_BYTES (14 * 4 * HSZ * 2)          /* 229376: up to 56 bf16 rows */
#define SMEM_BYTES (WS_BYTES + 512)          /* + gatev[2][64] */

__device__ __forceinline__ float sigm(float x) { return 1.f / (1.f + __expf(-x)); }
__device__ __forceinline__ float tanh_fast(float x) {
    return 1.f - __fdividef(2.f, __expf(2.f * x) + 1.f);
}

// acc.{lo,hi} += {bf16lo(w), bf16hi(w)} * h2.{lo,hi}   (packed fp32 FMA)
__device__ __forceinline__ void bffma2(unsigned long long& acc, unsigned w,
                                       unsigned long long h2) {
    asm("{\n\t"
        ".reg .b32 lo, hi;\n\t"
        ".reg .b64 wf;\n\t"
        "shl.b32 lo, %1, 16;\n\t"
        "and.b32 hi, %1, 0xFFFF0000;\n\t"
        "mov.b64 wf, {lo, hi};\n\t"
        "fma.rn.f32x2 %0, wf, %2, %0;\n\t"
        "}" : "+l"(acc) : "r"(w), "l"(h2));
}
__device__ __forceinline__ unsigned long long bf2f2(unsigned u) {
    unsigned long long r;
    asm("{\n\t"
        ".reg .b32 lo, hi;\n\t"
        "shl.b32 lo, %1, 16;\n\t"
        "and.b32 hi, %1, 0xFFFF0000;\n\t"
        "mov.b64 %0, {lo, hi};\n\t"
        "}" : "=l"(r) : "r"(u));
    return r;
}
__device__ __forceinline__ float2 unpackf2(unsigned long long v) {
    float2 r;
    asm("mov.b64 {%0, %1}, %2;" : "=f"(r.x), "=f"(r.y) : "l"(v));
    return r;
}
__device__ __forceinline__ unsigned ldrelaxed(const unsigned* p) {
    unsigned v;
    asm volatile("ld.relaxed.gpu.global.u32 %0, [%1];" : "=r"(v) : "l"(p));
    return v;
}
__device__ __forceinline__ void strel_u32(unsigned* p, unsigned v) {
    asm volatile("st.release.gpu.global.u32 [%0], %1;" :: "l"(p), "r"(v));
}
__device__ __forceinline__ void fence_acqrel() {
    asm volatile("fence.acq_rel.gpu;" ::: "memory");
}
__device__ __forceinline__ void st16cg(unsigned short* p, unsigned short v) {
    asm volatile("st.global.cg.u16 [%0], %1;" :: "l"(p), "h"(v));
}

template<int CNT>
__device__ __forceinline__ void run_steps(char* smem, float* gatev,
                                          int b, int base, int warp, int lane)
{
    const int half = warp & 1;
    const int rbase = warp >> 1;
    const uint4* wb = (const uint4*)(smem + half * 2048) + lane;

    float cst = 0.f;
    float xf = 0.f, xi = 0.f, xc = 0.f, xo = 0.f;
    if (warp == 0 && lane < CNT) {
        const float* xr = g_xproj;
        int j = base + lane;
        xf = __ldg(xr + j);
        xi = __ldg(xr + HSZ + j);
        xc = __ldg(xr + 2 * HSZ + j);
        xo = __ldg(xr + 3 * HSZ + j);
    }

    for (int t = 0; t < T_STEPS; t++) {
        // ---- load this warp's h half (bf16) and unpack to f32x2 ----
        const uint4* hp = (const uint4*)(g_hb + (t & 1) * HSZ + half * 1024) + lane;
        unsigned long long hv[16];
#pragma unroll
        for (int i = 0; i < 4; i++) {
            uint4 v = __ldcg(hp + i * 32);
            hv[4 * i + 0] = bf2f2(v.x);
            hv[4 * i + 1] = bf2f2(v.y);
            hv[4 * i + 2] = bf2f2(v.z);
            hv[4 * i + 3] = bf2f2(v.w);
        }

        // ---- GEMV half-rows, fully unrolled, two rows per iteration ----
#pragma unroll
        for (int m = 0; m + 1 < CNT; m += 2) {
            const int r0 = 4 * m + rbase;
            const int r1 = r0 + 4;
            const uint4* wA = wb + r0 * 256;
            const uint4* wB = wb + r1 * 256;
            unsigned long long accA = 0ull, accB = 0ull;
#pragma unroll
            for (int i = 0; i < 4; i++) {
                uint4 a = wA[i * 32];
                uint4 bq = wB[i * 32];
                bffma2(accA, a.x, hv[4 * i + 0]);
                bffma2(accA, a.y, hv[4 * i + 1]);
                bffma2(accA, a.z, hv[4 * i + 2]);
                bffma2(accA, a.w, hv[4 * i + 3]);
                bffma2(accB, bq.x, hv[4 * i + 0]);
                bffma2(accB, bq.y, hv[4 * i + 1]);
                bffma2(accB, bq.z, hv[4 * i + 2]);
                bffma2(accB, bq.w, hv[4 * i + 3]);
            }
            float2 a2 = unpackf2(accA), b2 = unpackf2(accB);
            float sA = a2.x + a2.y, sB = b2.x + b2.y;
#pragma unroll
            for (int o = 16; o > 0; o >>= 1) {
                sA += __shfl_down_sync(0xffffffffu, sA, o);
                sB += __shfl_down_sync(0xffffffffu, sB, o);
            }
            if (lane == 0) {
                gatev[half * 64 + r0] = sA;
                gatev[half * 64 + r1] = sB;
            }
        }
        if (CNT & 1) {                           // odd tail (CNT = 13)
            const int r0 = 4 * (CNT - 1) + rbase;
            const uint4* wA = wb + r0 * 256;
            unsigned long long accA = 0ull;
#pragma unroll
            for (int i = 0; i < 4; i++) {
                uint4 a = wA[i * 32];
                bffma2(accA, a.x, hv[4 * i + 0]);
                bffma2(accA, a.y, hv[4 * i + 1]);
                bffma2(accA, a.z, hv[4 * i + 2]);
                bffma2(accA, a.w, hv[4 * i + 3]);
            }
            float2 a2 = unpackf2(accA);
            float sA = a2.x + a2.y;
#pragma unroll
            for (int o = 16; o > 0; o >>= 1)
                sA += __shfl_down_sync(0xffffffffu, sA, o);
            if (lane == 0) gatev[half * 64 + r0] = sA;
        }
        __syncthreads();                         // (A) gatev complete

        // ---- warp 0: cell update, publish h_{t+1}, flag, poll all ----
        if (warp == 0) {
            if (lane < CNT) {
                float f  = sigm(gatev[lane]                + gatev[64 + lane]                + xf);
                float ig = sigm(gatev[CNT + lane]          + gatev[64 + CNT + lane]          + xi);
                float ch = tanh_fast(gatev[2 * CNT + lane] + gatev[64 + 2 * CNT + lane]      + xc);
                float o  = sigm(gatev[3 * CNT + lane]      + gatev[64 + 3 * CNT + lane]      + xo);
                float c  = f * cst + ig * ch;
                cst = c;
                unsigned short hb = __bfloat16_as_ushort(__float2bfloat16_rn(o * tanh_fast(c)));
                st16cg(&g_hb[((t + 1) & 1) * HSZ + base + lane], hb);
            }
            __syncwarp();                        // lanes' h-stores complete before flag
            if (lane == 0)
                strel_u32(&g_flags[b], (unsigned)(t + 1));  // single release store
            if (lane < CNT && t + 1 < T_STEPS) { // prefetch next x (off hot path)
                const float* xr = g_xproj + (size_t)(t + 1) * (4 * HSZ);
                int j = base + lane;
                xf = __ldg(xr + j);
                xi = __ldg(xr + HSZ + j);
                xc = __ldg(xr + 2 * HSZ + j);
                xo = __ldg(xr + 3 * HSZ + j);
            }
            // ---- all-to-all detection, graduated backoff ----
            const unsigned tgt = (unsigned)(t + 1);
            unsigned delay = 0;                  // first rounds: no sleep
            for (;;) {
                unsigned m0 = ldrelaxed(g_flags + lane);
                unsigned m1 = ldrelaxed(g_flags + 32 + lane);
                unsigned m2 = ldrelaxed(g_flags + 64 + lane);
                unsigned m3 = ldrelaxed(g_flags + 96 + lane);
                unsigned m4 = ldrelaxed(g_flags + 128 + lane);
                unsigned mn = min(min(min(m0, m1), min(m2, m3)), m4);
                if (__all_sync(0xffffffffu, mn >= tgt)) break;
                if (delay) __nanosleep(delay);
                delay = (delay == 0) ? 64 : min(delay * 2, 1024u);
            }
            fence_acqrel();                      // acquire: pair with release stores
        }
        __syncthreads();                         // (B) propagates acquire to all warps
    }
}

__global__ __launch_bounds__(RT, 1) void recur_kernel(
    const float* __restrict__ Uf, const float* __restrict__ Ui,
    const float* __restrict__ Uc, const float* __restrict__ Uo)
{
    extern __shared__ char smem[];
    float* gatev = (float*)(smem + WS_BYTES);   // [2][64] half-partials

    const int b = blockIdx.x;
    const int tid = threadIdx.x;
    const int warp = tid >> 5, lane = tid & 31;
    const int cnt  = (b < 124) ? 14 : 13;       // h-indices owned (sum = 2048)
    const int base = b * 13 + ((b < 124) ? b : 124);
    const int R = 4 * cnt;

    // ---- stage U rows into SMEM as packed bf16 pairs ----
    {
        const float* Us[4] = {Uf, Ui, Uc, Uo};
        for (int e = tid; e < R * 512; e += RT) {
            int r = e >> 9;
            int c4 = e & 511;
            int g = r / cnt;
            int k = r - g * cnt;
            float4 v = *(const float4*)(Us[g] + (size_t)(base + k) * HSZ + c4 * 4);
            unsigned lo = ((unsigned)__bfloat16_as_ushort(__float2bfloat16_rn(v.y)) << 16)
                        |  (unsigned)__bfloat16_as_ushort(__float2bfloat16_rn(v.x));
            unsigned hi = ((unsigned)__bfloat16_as_ushort(__float2bfloat16_rn(v.w)) << 16)
                        |  (unsigned)__bfloat16_as_ushort(__float2bfloat16_rn(v.z));
            *((uint2*)(smem + (size_t)r * 4096) + c4) = make_uint2(lo, hi);
        }
    }
    __syncthreads();

    if (cnt == 14) run_steps<14>(smem, gatev, b, base, warp, lane);
    else           run_steps<13>(smem, gatev, b, base, warp, lane);
}

// ---------------- head: fc + log_softmax over bf16 h ------------------------
__global__ __launch_bounds__(1024) void head_kernel(
    const float* __restrict__ fcw, const float* __restrict__ fcb,
    float* __restrict__ out)
{
    __shared__ float zs[OSZ];
    const int tid = threadIdx.x;
    const int warp = tid >> 5, lane = tid & 31;     // 32 warps, 2 outputs each
    const int o0 = 2 * warp, o1 = o0 + 1;
    const float* w0 = fcw + (size_t)o0 * HSZ;
    const float* w1 = fcw + (size_t)o1 * HSZ;
    float z0 = 0.f, z1 = 0.f;
#pragma unroll
    for (int i = 0; i < 8; i++) {
        int c = i * 256 + lane * 8;
        uint4 hq = *(const uint4*)(g_hb + c);       // 8 bf16 (final h, buf 0)
        float h0 = __uint_as_float(hq.x << 16), h1 = __uint_as_float(hq.x & 0xFFFF0000u);
        float h2 = __uint_as_float(hq.y << 16), h3 = __uint_as_float(hq.y & 0xFFFF0000u);
        float h4 = __uint_as_float(hq.z << 16), h5 = __uint_as_float(hq.z & 0xFFFF0000u);
        float h6 = __uint_as_float(hq.w << 16), h7 = __uint_as_float(hq.w & 0xFFFF0000u);
        float4 a0 = *(const float4*)(w0 + c);
        float4 a1 = *(const float4*)(w0 + c + 4);
        float4 b0 = *(const float4*)(w1 + c);
        float4 b1 = *(const float4*)(w1 + c + 4);
        z0 = fmaf(a0.x, h0, fmaf(a0.y, h1, fmaf(a0.z, h2, fmaf(a0.w, h3, z0))));
        z0 = fmaf(a1.x, h4, fmaf(a1.y, h5, fmaf(a1.z, h6, fmaf(a1.w, h7, z0))));
        z1 = fmaf(b0.x, h0, fmaf(b0.y, h1, fmaf(b0.z, h2, fmaf(b0.w, h3, z1))));
        z1 = fmaf(b1.x, h4, fmaf(b1.y, h5, fmaf(b1.z, h6, fmaf(b1.w, h7, z1))));
    }
#pragma unroll
    for (int o = 16; o > 0; o >>= 1) {
        z0 += __shfl_down_sync(0xffffffffu, z0, o);
        z1 += __shfl_down_sync(0xffffffffu, z1, o);
    }
    if (lane == 0) { zs[o0] = z0 + fcb[o0]; zs[o1] = z1 + fcb[o1]; }
    __syncthreads();
    if (warp == 0) {
        float a = zs[2 * lane], bq = zs[2 * lane + 1];
        float mx = fmaxf(a, bq);
#pragma unroll
        for (int o = 16; o > 0; o >>= 1) mx = fmaxf(mx, __shfl_xor_sync(0xffffffffu, mx, o));
        float s = expf(a - mx) + expf(bq - mx);
#pragma unroll
        for (int o = 16; o > 0; o >>= 1) s += __shfl_xor_sync(0xffffffffu, s, o);
        float lse = mx + logf(s);
        out[2 * lane]     = a - lse;
        out[2 * lane + 1] = bq - lse;
    }
}

// ---------------- launcher ---------------------------------------------------
extern "C" void kernel_launch(void* const* d_in, const int* in_sizes, int n_in,
                              void* d_out, int out_size)
{
    (void)in_sizes; (void)n_in; (void)out_size;
    const float* A    = (const float*)d_in[0];
    const float* Wf_w = (const float*)d_in[1];  const float* Wf_b = (const float*)d_in[2];
    const float* Uf_w = (const float*)d_in[3];  const float* Uf_b = (const float*)d_in[4];
    const float* Wi_w = (const float*)d_in[5];  const float* Wi_b = (const float*)d_in[6];
    const float* Ui_w = (const float*)d_in[7];  const float* Ui_b = (const float*)d_in[8];
    const float* Wc_w = (const float*)d_in[9];  const float* Wc_b = (const float*)d_in[10];
    const float* Uc_w = (const float*)d_in[11]; const float* Uc_b = (const float*)d_in[12];
    const float* Wo_w = (const float*)d_in[13]; const float* Wo_b = (const float*)d_in[14];
    const float* Uo_w = (const float*)d_in[15]; const float* Uo_b = (const float*)d_in[16];
    const float* fc_w = (const float*)d_in[17]; const float* fc_b = (const float*)d_in[18];
    float* out = (float*)d_out;

    cudaFuncSetAttribute(recur_kernel,
                         cudaFuncAttributeMaxDynamicSharedMemorySize, SMEM_BYTES);

    init_kernel<<<32, 256>>>();
    dim3 g(128, 32);
    xproj_kernel<<<g, 256>>>(A, Wf_w, Wi_w, Wc_w, Wo_w,
                             Wf_b, Wi_b, Wc_b, Wo_b,
                             Uf_b, Ui_b, Uc_b, Uo_b);
    recur_kernel<<<NBLK, RT, SMEM_BYTES>>>(Uf_w, Ui_w, Uc_w, Uo_w);
    head_kernel<<<1, 1024>>>(fc_w, fc_b, out);
}

// round 10
// speedup vs baseline: 1.8532x; 1.8532x over previous
#include <cuda_runtime.h>
#include <cuda_bf16.h>
#include <cstdint>

#define T_STEPS 4096
#define ISZ 1024
#define HSZ 2048
#define OSZ 64
#define NBLK 148
#define RT 256

// ---------------- device scratch (no allocations allowed) -------------------
__device__ float g_xproj[(size_t)T_STEPS * 4 * HSZ];  // [t][gate*H + j]
__device__ unsigned short g_hb[2 * HSZ];              // double-buffered h (bf16)
__device__ __align__(128) unsigned g_flags[160];      // per-block arrival flags
                                                      // [NBLK..159] = UINT_MAX pad
__device__ __align__(128) unsigned g_go_pad[32];      // [0] = broadcast epoch

// ---------------- init: zero h buffers + barrier state ----------------------
__global__ void init_kernel() {
    int i = blockIdx.x * blockDim.x + threadIdx.x;
    int n = blockDim.x * gridDim.x;
    for (int k = i; k < 2 * HSZ; k += n) g_hb[k] = 0;
    for (int k = i; k < 160; k += n) g_flags[k] = (k < NBLK) ? 0u : 0xFFFFFFFFu;
    if (i == 0) g_go_pad[0] = 0u;
}

// ---------------- x-projection GEMM ------------------------------------------
#define BM 128
#define BN 64
#define BK 16

__global__ __launch_bounds__(256) void xproj_kernel(
    const float* __restrict__ A,
    const float* __restrict__ W0, const float* __restrict__ W1,
    const float* __restrict__ W2, const float* __restrict__ W3,
    const float* __restrict__ Wb0, const float* __restrict__ Wb1,
    const float* __restrict__ Wb2, const float* __restrict__ Wb3,
    const float* __restrict__ Ub0, const float* __restrict__ Ub1,
    const float* __restrict__ Ub2, const float* __restrict__ Ub3)
{
    __shared__ float As[BK][BM + 4];
    __shared__ float Bs[BK][BN + 4];
    const int bn = blockIdx.x;
    const int bm = blockIdx.y;
    const int gate = bn >> 5;
    const int j0 = (bn & 31) * BN;
    const float* W  = (gate == 0) ? W0  : (gate == 1) ? W1  : (gate == 2) ? W2  : W3;
    const float* Wb = (gate == 0) ? Wb0 : (gate == 1) ? Wb1 : (gate == 2) ? Wb2 : Wb3;
    const float* Ub = (gate == 0) ? Ub0 : (gate == 1) ? Ub1 : (gate == 2) ? Ub2 : Ub3;
    const int m0 = bm * BM;
    const int tid = threadIdx.x;
    const int tm = tid >> 4, tn = tid & 15;

    float acc[8][4];
#pragma unroll
    for (int i = 0; i < 8; i++)
#pragma unroll
        for (int j = 0; j < 4; j++) acc[i][j] = 0.f;

    for (int k0 = 0; k0 < ISZ; k0 += BK) {
#pragma unroll
        for (int it = 0; it < 2; it++) {
            int e = tid + it * 256;
            int row = e >> 2, kq = e & 3;
            float4 v = *(const float4*)(A + (size_t)(m0 + row) * ISZ + k0 + kq * 4);
            As[kq * 4 + 0][row] = v.x; As[kq * 4 + 1][row] = v.y;
            As[kq * 4 + 2][row] = v.z; As[kq * 4 + 3][row] = v.w;
        }
        {
            int row = tid >> 2, kq = tid & 3;
            float4 v = *(const float4*)(W + (size_t)(j0 + row) * ISZ + k0 + kq * 4);
            Bs[kq * 4 + 0][row] = v.x; Bs[kq * 4 + 1][row] = v.y;
            Bs[kq * 4 + 2][row] = v.z; Bs[kq * 4 + 3][row] = v.w;
        }
        __syncthreads();
#pragma unroll
        for (int k = 0; k < BK; k++) {
            float a[8], bb[4];
#pragma unroll
            for (int i = 0; i < 8; i++) a[i] = As[k][tm * 8 + i];
#pragma unroll
            for (int j = 0; j < 4; j++) bb[j] = Bs[k][tn * 4 + j];
#pragma unroll
            for (int i = 0; i < 8; i++)
#pragma unroll
                for (int j = 0; j < 4; j++)
                    acc[i][j] = fmaf(a[i], bb[j], acc[i][j]);
        }
        __syncthreads();
    }

    float bias[4];
#pragma unroll
    for (int j = 0; j < 4; j++) {
        int col = j0 + tn * 4 + j;
        bias[j] = Wb[col] + Ub[col];
    }
#pragma unroll
    for (int i = 0; i < 8; i++) {
        int row = m0 + tm * 8 + i;
        float4 v = make_float4(acc[i][0] + bias[0], acc[i][1] + bias[1],
                               acc[i][2] + bias[2], acc[i][3] + bias[3]);
        *(float4*)(g_xproj + (size_t)row * (4 * HSZ) + gate * HSZ + j0 + tn * 4) = v;
    }
}

// ---------------- persistent recurrence kernel ------------------------------
#define WS_BYTES (14 * 4 * HSZ * 2)          /* 229376: up to 56 bf16 rows */
#define SMEM_BYTES (WS_BYTES + 512)          /* + gatev[2][64] */

__device__ __forceinline__ float sigm(float x) { return 1.f / (1.f + __expf(-x)); }
__device__ __forceinline__ float tanh_fast(float x) {
    return 1.f - __fdividef(2.f, __expf(2.f * x) + 1.f);
}

// acc.{lo,hi} += {bf16lo(w), bf16hi(w)} * h2.{lo,hi}   (packed fp32 FMA)
__device__ __forceinline__ void bffma2(unsigned long long& acc, unsigned w,
                                       unsigned long long h2) {
    asm("{\n\t"
        ".reg .b32 lo, hi;\n\t"
        ".reg .b64 wf;\n\t"
        "shl.b32 lo, %1, 16;\n\t"
        "and.b32 hi, %1, 0xFFFF0000;\n\t"
        "mov.b64 wf, {lo, hi};\n\t"
        "fma.rn.f32x2 %0, wf, %2, %0;\n\t"
        "}" : "+l"(acc) : "r"(w), "l"(h2));
}
__device__ __forceinline__ unsigned long long bf2f2(unsigned u) {
    unsigned long long r;
    asm("{\n\t"
        ".reg .b32 lo, hi;\n\t"
        "shl.b32 lo, %1, 16;\n\t"
        "and.b32 hi, %1, 0xFFFF0000;\n\t"
        "mov.b64 %0, {lo, hi};\n\t"
        "}" : "=l"(r) : "r"(u));
    return r;
}
__device__ __forceinline__ float2 unpackf2(unsigned long long v) {
    float2 r;
    asm("mov.b64 {%0, %1}, %2;" : "=f"(r.x), "=f"(r.y) : "l"(v));
    return r;
}
__device__ __forceinline__ unsigned ldrelaxed(const unsigned* p) {
    unsigned v;
    asm volatile("ld.relaxed.gpu.global.u32 %0, [%1];" : "=r"(v) : "l"(p));
    return v;
}
__device__ __forceinline__ unsigned ldacq(const unsigned* p) {
    unsigned v;
    asm volatile("ld.acquire.gpu.global.u32 %0, [%1];" : "=r"(v) : "l"(p));
    return v;
}
__device__ __forceinline__ void strel_u32(unsigned* p, unsigned v) {
    asm volatile("st.release.gpu.global.u32 [%0], %1;" :: "l"(p), "r"(v));
}
__device__ __forceinline__ void fence_acqrel() {
    asm volatile("fence.acq_rel.gpu;" ::: "memory");
}
__device__ __forceinline__ void st16cg(unsigned short* p, unsigned short v) {
    asm volatile("st.global.cg.u16 [%0], %1;" :: "l"(p), "h"(v));
}

template<int CNT>
__device__ __forceinline__ void run_steps(char* smem, float* gatev,
                                          int b, int base, int warp, int lane)
{
    const int half = warp & 1;
    const int rbase = warp >> 1;
    const uint4* wb = (const uint4*)(smem + half * 2048) + lane;

    float cst = 0.f;
    float xf = 0.f, xi = 0.f, xc = 0.f, xo = 0.f;
    if (warp == 0 && lane < CNT) {
        const float* xr = g_xproj;
        int j = base + lane;
        xf = __ldg(xr + j);
        xi = __ldg(xr + HSZ + j);
        xc = __ldg(xr + 2 * HSZ + j);
        xo = __ldg(xr + 3 * HSZ + j);
    }

    for (int t = 0; t < T_STEPS; t++) {
        // ---- load this warp's h half (bf16) and unpack to f32x2 ----
        const uint4* hp = (const uint4*)(g_hb + (t & 1) * HSZ + half * 1024) + lane;
        unsigned long long hv[16];
#pragma unroll
        for (int i = 0; i < 4; i++) {
            uint4 v = __ldcg(hp + i * 32);
            hv[4 * i + 0] = bf2f2(v.x);
            hv[4 * i + 1] = bf2f2(v.y);
            hv[4 * i + 2] = bf2f2(v.z);
            hv[4 * i + 3] = bf2f2(v.w);
        }

        // ---- GEMV half-rows, fully unrolled, two rows per iteration ----
#pragma unroll
        for (int m = 0; m + 1 < CNT; m += 2) {
            const int r0 = 4 * m + rbase;
            const int r1 = r0 + 4;
            const uint4* wA = wb + r0 * 256;
            const uint4* wB = wb + r1 * 256;
            unsigned long long accA = 0ull, accB = 0ull;
#pragma unroll
            for (int i = 0; i < 4; i++) {
                uint4 a = wA[i * 32];
                uint4 bq = wB[i * 32];
                bffma2(accA, a.x, hv[4 * i + 0]);
                bffma2(accA, a.y, hv[4 * i + 1]);
                bffma2(accA, a.z, hv[4 * i + 2]);
                bffma2(accA, a.w, hv[4 * i + 3]);
                bffma2(accB, bq.x, hv[4 * i + 0]);
                bffma2(accB, bq.y, hv[4 * i + 1]);
                bffma2(accB, bq.z, hv[4 * i + 2]);
                bffma2(accB, bq.w, hv[4 * i + 3]);
            }
            float2 a2 = unpackf2(accA), b2 = unpackf2(accB);
            float sA = a2.x + a2.y, sB = b2.x + b2.y;
#pragma unroll
            for (int o = 16; o > 0; o >>= 1) {
                sA += __shfl_down_sync(0xffffffffu, sA, o);
                sB += __shfl_down_sync(0xffffffffu, sB, o);
            }
            if (lane == 0) {
                gatev[half * 64 + r0] = sA;
                gatev[half * 64 + r1] = sB;
            }
        }
        if (CNT & 1) {                           // odd tail (CNT = 13)
            const int r0 = 4 * (CNT - 1) + rbase;
            const uint4* wA = wb + r0 * 256;
            unsigned long long accA = 0ull;
#pragma unroll
            for (int i = 0; i < 4; i++) {
                uint4 a = wA[i * 32];
                bffma2(accA, a.x, hv[4 * i + 0]);
                bffma2(accA, a.y, hv[4 * i + 1]);
                bffma2(accA, a.z, hv[4 * i + 2]);
                bffma2(accA, a.w, hv[4 * i + 3]);
            }
            float2 a2 = unpackf2(accA);
            float sA = a2.x + a2.y;
#pragma unroll
            for (int o = 16; o > 0; o >>= 1)
                sA += __shfl_down_sync(0xffffffffu, sA, o);
            if (lane == 0) gatev[half * 64 + r0] = sA;
        }
        __syncthreads();                         // (A) gatev complete

        // ---- warp 0: cell update, publish h_{t+1}, arrive; detect/broadcast
        if (warp == 0) {
            if (lane < CNT) {
                float f  = sigm(gatev[lane]                + gatev[64 + lane]                + xf);
                float ig = sigm(gatev[CNT + lane]          + gatev[64 + CNT + lane]          + xi);
                float ch = tanh_fast(gatev[2 * CNT + lane] + gatev[64 + 2 * CNT + lane]      + xc);
                float o  = sigm(gatev[3 * CNT + lane]      + gatev[64 + 3 * CNT + lane]      + xo);
                float c  = f * cst + ig * ch;
                cst = c;
                unsigned short hb = __bfloat16_as_ushort(__float2bfloat16_rn(o * tanh_fast(c)));
                st16cg(&g_hb[((t + 1) & 1) * HSZ + base + lane], hb);
            }
            __syncwarp();                        // lanes' h-stores before arrival flag
            if (lane == 0)
                strel_u32(&g_flags[b], (unsigned)(t + 1));  // parallel arrival
            if (lane < CNT && t + 1 < T_STEPS) { // prefetch next x (off hot path)
                const float* xr = g_xproj + (size_t)(t + 1) * (4 * HSZ);
                int j = base + lane;
                xf = __ldg(xr + j);
                xi = __ldg(xr + HSZ + j);
                xc = __ldg(xr + 2 * HSZ + j);
                xo = __ldg(xr + 3 * HSZ + j);
            }
            const unsigned tgt = (unsigned)(t + 1);
            if (b == 0) {
                // ---- sole detector: one warp polls the 148 flags ----
                for (;;) {
                    unsigned m0 = ldrelaxed(g_flags + lane);
                    unsigned m1 = ldrelaxed(g_flags + 32 + lane);
                    unsigned m2 = ldrelaxed(g_flags + 64 + lane);
                    unsigned m3 = ldrelaxed(g_flags + 96 + lane);
                    unsigned m4 = ldrelaxed(g_flags + 128 + lane);
                    unsigned mn = min(min(min(m0, m1), min(m2, m3)), m4);
                    if (__all_sync(0xffffffffu, mn >= tgt)) break;
                }
                fence_acqrel();                  // upgrade observed flags to acquire
                if (lane == 0)
                    strel_u32(&g_go_pad[0], tgt);// broadcast epoch (own line)
            } else if (lane == 0) {
                // ---- 147 pollers on the read-mostly go line (R5-proven) ----
                while (ldacq(&g_go_pad[0]) < tgt) { }
            }
        }
        __syncthreads();                         // (B) propagates acquire to all warps
    }
}

__global__ __launch_bounds__(RT, 1) void recur_kernel(
    const float* __restrict__ Uf, const float* __restrict__ Ui,
    const float* __restrict__ Uc, const float* __restrict__ Uo)
{
    extern __shared__ char smem[];
    float* gatev = (float*)(smem + WS_BYTES);   // [2][64] half-partials

    const int b = blockIdx.x;
    const int tid = threadIdx.x;
    const int warp = tid >> 5, lane = tid & 31;
    const int cnt  = (b < 124) ? 14 : 13;       // h-indices owned (sum = 2048)
    const int base = b * 13 + ((b < 124) ? b : 124);
    const int R = 4 * cnt;

    // ---- stage U rows into SMEM as packed bf16 pairs ----
    {
        const float* Us[4] = {Uf, Ui, Uc, Uo};
        for (int e = tid; e < R * 512; e += RT) {
            int r = e >> 9;
            int c4 = e & 511;
            int g = r / cnt;
            int k = r - g * cnt;
            float4 v = *(const float4*)(Us[g] + (size_t)(base + k) * HSZ + c4 * 4);
            unsigned lo = ((unsigned)__bfloat16_as_ushort(__float2bfloat16_rn(v.y)) << 16)
                        |  (unsigned)__bfloat16_as_ushort(__float2bfloat16_rn(v.x));
            unsigned hi = ((unsigned)__bfloat16_as_ushort(__float2bfloat16_rn(v.w)) << 16)
                        |  (unsigned)__bfloat16_as_ushort(__float2bfloat16_rn(v.z));
            *((uint2*)(smem + (size_t)r * 4096) + c4) = make_uint2(lo, hi);
        }
    }
    __syncthreads();

    if (cnt == 14) run_steps<14>(smem, gatev, b, base, warp, lane);
    else           run_steps<13>(smem, gatev, b, base, warp, lane);
}

// ---------------- head: fc + log_softmax over bf16 h ------------------------
__global__ __launch_bounds__(1024) void head_kernel(
    const float* __restrict__ fcw, const float* __restrict__ fcb,
    float* __restrict__ out)
{
    __shared__ float zs[OSZ];
    const int tid = threadIdx.x;
    const int warp = tid >> 5, lane = tid & 31;     // 32 warps, 2 outputs each
    const int o0 = 2 * warp, o1 = o0 + 1;
    const float* w0 = fcw + (size_t)o0 * HSZ;
    const float* w1 = fcw + (size_t)o1 * HSZ;
    float z0 = 0.f, z1 = 0.f;
#pragma unroll
    for (int i = 0; i < 8; i++) {
        int c = i * 256 + lane * 8;
        uint4 hq = *(const uint4*)(g_hb + c);       // 8 bf16 (final h, buf 0)
        float h0 = __uint_as_float(hq.x << 16), h1 = __uint_as_float(hq.x & 0xFFFF0000u);
        float h2 = __uint_as_float(hq.y << 16), h3 = __uint_as_float(hq.y & 0xFFFF0000u);
        float h4 = __uint_as_float(hq.z << 16), h5 = __uint_as_float(hq.z & 0xFFFF0000u);
        float h6 = __uint_as_float(hq.w << 16), h7 = __uint_as_float(hq.w & 0xFFFF0000u);
        float4 a0 = *(const float4*)(w0 + c);
        float4 a1 = *(const float4*)(w0 + c + 4);
        float4 b0 = *(const float4*)(w1 + c);
        float4 b1 = *(const float4*)(w1 + c + 4);
        z0 = fmaf(a0.x, h0, fmaf(a0.y, h1, fmaf(a0.z, h2, fmaf(a0.w, h3, z0))));
        z0 = fmaf(a1.x, h4, fmaf(a1.y, h5, fmaf(a1.z, h6, fmaf(a1.w, h7, z0))));
        z1 = fmaf(b0.x, h0, fmaf(b0.y, h1, fmaf(b0.z, h2, fmaf(b0.w, h3, z1))));
        z1 = fmaf(b1.x, h4, fmaf(b1.y, h5, fmaf(b1.z, h6, fmaf(b1.w, h7, z1))));
    }
#pragma unroll
    for (int o = 16; o > 0; o >>= 1) {
        z0 += __shfl_down_sync(0xffffffffu, z0, o);
        z1 += __shfl_down_sync(0xffffffffu, z1, o);
    }
    if (lane == 0) { zs[o0] = z0 + fcb[o0]; zs[o1] = z1 + fcb[o1]; }
    __syncthreads();
    if (warp == 0) {
        float a = zs[2 * lane], bq = zs[2 * lane + 1];
        float mx = fmaxf(a, bq);
#pragma unroll
        for (int o = 16; o > 0; o >>= 1) mx = fmaxf(mx, __shfl_xor_sync(0xffffffffu, mx, o));
        float s = expf(a - mx) + expf(bq - mx);
#pragma unroll
        for (int o = 16; o > 0; o >>= 1) s += __shfl_xor_sync(0xffffffffu, s, o);
        float lse = mx + logf(s);
        out[2 * lane]     = a - lse;
        out[2 * lane + 1] = bq - lse;
    }
}

// ---------------- launcher ---------------------------------------------------
extern "C" void kernel_launch(void* const* d_in, const int* in_sizes, int n_in,
                              void* d_out, int out_size)
{
    (void)in_sizes; (void)n_in; (void)out_size;
    const float* A    = (const float*)d_in[0];
    const float* Wf_w = (const float*)d_in[1];  const float* Wf_b = (const float*)d_in[2];
    const float* Uf_w = (const float*)d_in[3];  const float* Uf_b = (const float*)d_in[4];
    const float* Wi_w = (const float*)d_in[5];  const float* Wi_b = (const float*)d_in[6];
    const float* Ui_w = (const float*)d_in[7];  const float* Ui_b = (const float*)d_in[8];
    const float* Wc_w = (const float*)d_in[9];  const float* Wc_b = (const float*)d_in[10];
    const float* Uc_w = (const float*)d_in[11]; const float* Uc_b = (const float*)d_in[12];
    const float* Wo_w = (const float*)d_in[13]; const float* Wo_b = (const float*)d_in[14];
    const float* Uo_w = (const float*)d_in[15]; const float* Uo_b = (const float*)d_in[16];
    const float* fc_w = (const float*)d_in[17]; const float* fc_b = (const float*)d_in[18];
    float* out = (float*)d_out;

    cudaFuncSetAttribute(recur_kernel,
                         cudaFuncAttributeMaxDynamicSharedMemorySize, SMEM_BYTES);

    init_kernel<<<32, 256>>>();
    dim3 g(128, 32);
    xproj_kernel<<<g, 256>>>(A, Wf_w, Wi_w, Wc_w, Wo_w,
                             Wf_b, Wi_b, Wc_b, Wo_b,
                             Uf_b, Ui_b, Uc_b, Uo_b);
    recur_kernel<<<NBLK, RT, SMEM_BYTES>>>(Uf_w, Ui_w, Uc_w, Uo_w);
    head_kernel<<<1, 1024>>>(fc_w, fc_b, out);
}